// round 1
// baseline (speedup 1.0000x reference)
#include <cuda_runtime.h>

#define T_SEQ 2048
#define B_SZ  512
#define H_SZ  32

// Scratch (static __device__ arrays are the allowed scratch mechanism)
__device__ float g_h0[T_SEQ * B_SZ * H_SZ];                 // 134 MB
__device__ float g_xp1[(size_t)T_SEQ * B_SZ * 4 * H_SZ];    // 537 MB

typedef unsigned long long u64;

// ---------- packed f32x2 helpers (Blackwell dual-issue fp32 path) ----------
__device__ __forceinline__ u64 pack2(float a, float b) {
    u64 d; asm("mov.b64 %0,{%1,%2};" : "=l"(d) : "f"(a), "f"(b)); return d;
}
__device__ __forceinline__ void unpack2(u64 v, float& a, float& b) {
    asm("mov.b64 {%0,%1},%2;" : "=f"(a), "=f"(b) : "l"(v));
}
__device__ __forceinline__ u64 fma2(u64 a, u64 b, u64 c) {
    u64 d; asm("fma.rn.f32x2 %0,%1,%2,%3;" : "=l"(d) : "l"(a), "l"(b), "l"(c)); return d;
}

// ---------- fast activations (ex2/rcp approx: ~1e-6 err, MUFU pipe) ----------
__device__ __forceinline__ float ex2f(float x) { float y; asm("ex2.approx.ftz.f32 %0,%1;" : "=f"(y) : "f"(x)); return y; }
__device__ __forceinline__ float rcpf(float x) { float y; asm("rcp.approx.ftz.f32 %0,%1;" : "=f"(y) : "f"(x)); return y; }
__device__ __forceinline__ float sigm(float x)  { return rcpf(1.f + ex2f(-1.4426950408889634f * x)); }
__device__ __forceinline__ float tanhf_(float x){ float e = ex2f(2.8853900817779268f * x); return 1.f - 2.f * rcpf(e + 1.f); }

// =====================================================================
// Layer 0: one warp per batch element, whole T loop in-kernel.
// Gates paired (i,f) / (g,o) into f32x2 lanes; W_hh rows in registers.
// h broadcast via per-warp smem stored duplicated {h,h} -> LDS.64.
// =====================================================================
__global__ void __launch_bounds__(128, 1)
k_layer0(const float* __restrict__ x, const float* __restrict__ Wih,
         const float* __restrict__ Whh, const float* __restrict__ bih,
         const float* __restrict__ bhh)
{
    __shared__ __align__(16) float hb[4][2][64];
    const int w = threadIdx.x >> 5, j = threadIdx.x & 31;
    const int b = blockIdx.x * 4 + w;

    u64 w_if[32], w_go[32];
#pragma unroll
    for (int k = 0; k < 32; k++) {
        w_if[k] = pack2(Whh[j * 32 + k],        Whh[(32 + j) * 32 + k]);
        w_go[k] = pack2(Whh[(64 + j) * 32 + k], Whh[(96 + j) * 32 + k]);
    }
    const u64 wx_if = pack2(Wih[j],      Wih[32 + j]);
    const u64 wx_go = pack2(Wih[64 + j], Wih[96 + j]);
    const u64 bs_if = pack2(bih[j] + bhh[j],           bih[32 + j] + bhh[32 + j]);
    const u64 bs_go = pack2(bih[64 + j] + bhh[64 + j], bih[96 + j] + bhh[96 + j]);

    *reinterpret_cast<u64*>(&hb[w][0][2 * j]) = 0ull;  // h(-1) = 0
    float c = 0.f;
    float* h0o = g_h0 + b * 32 + j;
    float xt = x[b];   // x[t=0, b]  (IN == 1)
    int p = 0;
    __syncwarp();

#pragma unroll 1
    for (int t = 0; t < T_SEQ; t++) {
        float xn = x[min(t + 1, T_SEQ - 1) * B_SZ + b];     // prefetch next x
        u64 xs  = pack2(xt, xt);
        u64 aif = fma2(xs, wx_if, bs_if);
        u64 ago = fma2(xs, wx_go, bs_go);
        const u64* hv = reinterpret_cast<const u64*>(hb[w][p]);
#pragma unroll
        for (int k = 0; k < 32; k++) {
            u64 h2 = hv[k];
            aif = fma2(h2, w_if[k], aif);
            ago = fma2(h2, w_go[k], ago);
        }
        float gi, gf, gg, go;
        unpack2(aif, gi, gf); unpack2(ago, gg, go);
        gi = sigm(gi); gf = sigm(gf); gg = tanhf_(gg); go = sigm(go);
        c = gf * c + gi * gg;
        float h = go * tanhf_(c);
        p ^= 1;
        *reinterpret_cast<u64*>(&hb[w][p][2 * j]) = pack2(h, h);
        h0o[t * (B_SZ * 32)] = h;                           // coalesced 128B/warp
        __syncwarp();
        xt = xn;
    }
}

// =====================================================================
// xp1 = h0 @ W_ih1^T + (b_ih1 + b_hh1): fully parallel over T*B rows.
// Warp per row (strided), weights in regs, same f32x2 gate pairing.
// Output stored packed: row-major [row][ {i,f}[32] , {g,o}[32] ] as u64.
// =====================================================================
__global__ void __launch_bounds__(256)
k_proj1(const float* __restrict__ Wih, const float* __restrict__ bih,
        const float* __restrict__ bhh)
{
    __shared__ __align__(16) float sh[8][2][64];
    const int w = threadIdx.x >> 5, j = threadIdx.x & 31;
    const int gw = blockIdx.x * 8 + w;
    const int nw = gridDim.x * 8;
    const int NROW = T_SEQ * B_SZ;

    u64 w_if[32], w_go[32];
#pragma unroll
    for (int k = 0; k < 32; k++) {
        w_if[k] = pack2(Wih[j * 32 + k],        Wih[(32 + j) * 32 + k]);
        w_go[k] = pack2(Wih[(64 + j) * 32 + k], Wih[(96 + j) * 32 + k]);
    }
    const u64 bs_if = pack2(bih[j] + bhh[j],           bih[32 + j] + bhh[32 + j]);
    const u64 bs_go = pack2(bih[64 + j] + bhh[64 + j], bih[96 + j] + bhh[96 + j]);

    u64* xpu = reinterpret_cast<u64*>(g_xp1);

    int p = 0;
    float v = (gw < NROW) ? g_h0[gw * 32 + j] : 0.f;
    for (int row = gw; row < NROW; row += nw) {
        const int nrow = row + nw;
        *reinterpret_cast<u64*>(&sh[w][p][2 * j]) = pack2(v, v);
        float vn = (nrow < NROW) ? g_h0[nrow * 32 + j] : 0.f;  // prefetch
        __syncwarp();
        u64 aif = bs_if, ago = bs_go;
        const u64* hv = reinterpret_cast<const u64*>(sh[w][p]);
#pragma unroll
        for (int k = 0; k < 32; k++) {
            u64 h2 = hv[k];
            aif = fma2(h2, w_if[k], aif);
            ago = fma2(h2, w_go[k], ago);
        }
        xpu[row * 64 + j]      = aif;   // {i,f} pair, coalesced STG.64
        xpu[row * 64 + 32 + j] = ago;   // {g,o} pair
        v = vn; p ^= 1;
    }
}

// =====================================================================
// Layer 1 (recurrent only; input preacts streamed from g_xp1, 4-deep
// prefetch) + fused dense head (shfl butterfly, off the critical path).
// =====================================================================
__global__ void __launch_bounds__(128, 1)
k_layer1(const float* __restrict__ Whh, const float* __restrict__ Wd,
         const float* __restrict__ bd, float* __restrict__ out)
{
    __shared__ __align__(16) float hb[4][2][64];
    const int w = threadIdx.x >> 5, j = threadIdx.x & 31;
    const int b = blockIdx.x * 4 + w;

    u64 w_if[32], w_go[32];
#pragma unroll
    for (int k = 0; k < 32; k++) {
        w_if[k] = pack2(Whh[j * 32 + k],        Whh[(32 + j) * 32 + k]);
        w_go[k] = pack2(Whh[(64 + j) * 32 + k], Whh[(96 + j) * 32 + k]);
    }
    const float wd  = Wd[j];
    const float bdv = bd[0];
    const u64* xpu = reinterpret_cast<const u64*>(g_xp1);

    *reinterpret_cast<u64*>(&hb[w][0][2 * j]) = 0ull;
    float c = 0.f;
    int p = 0;

    u64 pif[4], pgo[4];
#pragma unroll
    for (int t = 0; t < 4; t++) {
        int base = (t * B_SZ + b) * 64 + j;
        pif[t] = xpu[base];
        pgo[t] = xpu[base + 32];
    }
    __syncwarp();

#pragma unroll 4
    for (int t = 0; t < T_SEQ; t++) {
        u64 aif = pif[t & 3];
        u64 ago = pgo[t & 3];
        {   // prefetch t+4 (clamped; harmless duplicate loads at the tail)
            int tp = min(t + 4, T_SEQ - 1);
            int base = (tp * B_SZ + b) * 64 + j;
            pif[t & 3] = xpu[base];
            pgo[t & 3] = xpu[base + 32];
        }
        const u64* hv = reinterpret_cast<const u64*>(hb[w][p]);
#pragma unroll
        for (int k = 0; k < 32; k++) {
            u64 h2 = hv[k];
            aif = fma2(h2, w_if[k], aif);
            ago = fma2(h2, w_go[k], ago);
        }
        float gi, gf, gg, go;
        unpack2(aif, gi, gf); unpack2(ago, gg, go);
        gi = sigm(gi); gf = sigm(gf); gg = tanhf_(gg); go = sigm(go);
        c = gf * c + gi * gg;
        float h = go * tanhf_(c);
        p ^= 1;
        *reinterpret_cast<u64*>(&hb[w][p][2 * j]) = pack2(h, h);

        // fused dense head: y[t,b] = sum_j h_j * Wd_j + bd
        float y = h * wd;
#pragma unroll
        for (int off = 16; off > 0; off >>= 1)
            y += __shfl_xor_sync(0xffffffffu, y, off);
        if (j == 0) out[t * B_SZ + b] = y + bdv;
        __syncwarp();
    }
}

// =====================================================================
extern "C" void kernel_launch(void* const* d_in, const int* in_sizes, int n_in,
                              void* d_out, int out_size)
{
    const float* x    = (const float*)d_in[0];
    const float* Wih0 = (const float*)d_in[1];
    const float* Whh0 = (const float*)d_in[2];
    const float* bih0 = (const float*)d_in[3];
    const float* bhh0 = (const float*)d_in[4];
    const float* Wih1 = (const float*)d_in[5];
    const float* Whh1 = (const float*)d_in[6];
    const float* bih1 = (const float*)d_in[7];
    const float* bhh1 = (const float*)d_in[8];
    const float* Wd   = (const float*)d_in[9];
    const float* bd   = (const float*)d_in[10];

    k_layer0<<<128, 128>>>(x, Wih0, Whh0, bih0, bhh0);
    k_proj1<<<2048, 256>>>(Wih1, bih1, bhh1);
    k_layer1<<<128, 128>>>(Whh1, Wd, bd, (float*)d_out);
}

// round 2
// speedup vs baseline: 2.1632x; 2.1632x over previous
#include <cuda_runtime.h>

#define T_SEQ 2048
#define B_SZ  512

// h1 output scratch for the deferred dense head (134 MB)
__device__ __align__(16) float g_h1[(size_t)T_SEQ * B_SZ * 32];

typedef unsigned long long u64;

// ---------- packed f32x2 helpers ----------
__device__ __forceinline__ u64 pack2(float a, float b) {
    u64 d; asm("mov.b64 %0,{%1,%2};" : "=l"(d) : "f"(a), "f"(b)); return d;
}
__device__ __forceinline__ void unpack2(u64 v, float& a, float& b) {
    asm("mov.b64 {%0,%1},%2;" : "=f"(a), "=f"(b) : "l"(v));
}
__device__ __forceinline__ u64 fma2(u64 a, u64 b, u64 c) {
    u64 d; asm("fma.rn.f32x2 %0,%1,%2,%3;" : "=l"(d) : "l"(a), "l"(b), "l"(c)); return d;
}

// ---------- fast activations (MUFU ex2/rcp, ~1e-6 err — validated R1) ----------
__device__ __forceinline__ float ex2f(float x) { float y; asm("ex2.approx.ftz.f32 %0,%1;" : "=f"(y) : "f"(x)); return y; }
__device__ __forceinline__ float rcpf(float x) { float y; asm("rcp.approx.ftz.f32 %0,%1;" : "=f"(y) : "f"(x)); return y; }
__device__ __forceinline__ float sigm(float x)  { return rcpf(1.f + ex2f(-1.4426950408889634f * x)); }
__device__ __forceinline__ float tanhf_(float x){ float e = ex2f(2.8853900817779268f * x); return 1.f - 2.f * rcpf(e + 1.f); }

// =====================================================================
// Fused 2-layer LSTM: 3 specialized warps per batch element.
//   role 0: layer-0 cell      (computes h0[t] at tick n = t)
//   role 1: input projection  (xp1[t] = W_ih1 h0[t] + b, at tick n = t+1)
//   role 2: layer-1 cell      (h1[t] from xp1[t] + W_hh1 h1[t-1], tick n = t+2)
// Block = 4 elements x 3 roles = 12 warps; warp->SMSP mapping (wid%4)
// puts exactly one warp of each role on every SMSP.
// One __syncthreads per tick; smem double-buffer rings between stages.
// =====================================================================
__global__ void __launch_bounds__(384, 1)
k_fused(const float* __restrict__ x,
        const float* __restrict__ Wih0, const float* __restrict__ Whh0,
        const float* __restrict__ bih0, const float* __restrict__ bhh0,
        const float* __restrict__ Wih1, const float* __restrict__ Whh1,
        const float* __restrict__ bih1, const float* __restrict__ bhh1)
{
    __shared__ __align__(16) float h0ring[4][2][64];   // duplicated {h,h} pairs
    __shared__ __align__(16) u64   pring[4][2][64];    // [j]={i,f} preact, [32+j]={g,o}
    __shared__ __align__(16) float h1buf[4][64];       // duplicated {h,h} pairs

    const int tid  = threadIdx.x;
    const int wid  = tid >> 5, j = tid & 31;
    const int e    = wid & 3;          // element slot in block
    const int role = wid >> 2;         // 0=L0, 1=proj, 2=L1
    const int b    = blockIdx.x * 4 + e;

    // zero initial hidden states
    for (int i = tid; i < 4 * 2 * 64; i += 384) ((float*)h0ring)[i] = 0.f;
    for (int i = tid; i < 4 * 64;     i += 384) ((float*)h1buf)[i]  = 0.f;

    // per-role weight matrix -> 64 u64 regs of gate-pair columns
    const float* Wsrc = (role == 0) ? Whh0 : (role == 1) ? Wih1 : Whh1;
    u64 w_if[32], w_go[32];
#pragma unroll
    for (int k = 0; k < 32; k++) {
        w_if[k] = pack2(Wsrc[j * 32 + k],        Wsrc[(32 + j) * 32 + k]);
        w_go[k] = pack2(Wsrc[(64 + j) * 32 + k], Wsrc[(96 + j) * 32 + k]);
    }

    u64 wx_if = 0, wx_go = 0, bs_if = 0, bs_go = 0;
    if (role == 0) {
        wx_if = pack2(Wih0[j],      Wih0[32 + j]);
        wx_go = pack2(Wih0[64 + j], Wih0[96 + j]);
        bs_if = pack2(bih0[j] + bhh0[j],           bih0[32 + j] + bhh0[32 + j]);
        bs_go = pack2(bih0[64 + j] + bhh0[64 + j], bih0[96 + j] + bhh0[96 + j]);
    } else if (role == 1) {
        bs_if = pack2(bih1[j] + bhh1[j],           bih1[32 + j] + bhh1[32 + j]);
        bs_go = pack2(bih1[64 + j] + bhh1[64 + j], bih1[96 + j] + bhh1[96 + j]);
    }

    float c  = 0.f;                    // cell state (roles 0 and 2)
    float xt = x[b];                   // x[t=0] (IN == 1)

    __syncthreads();

#pragma unroll 1
    for (int n = 0; n < T_SEQ + 2; n++) {
        if (role == 0) {
            if (n < T_SEQ) {
                float xn = (n + 1 < T_SEQ) ? x[(n + 1) * B_SZ + b] : 0.f;
                u64 xs  = pack2(xt, xt);
                u64 aif = fma2(xs, wx_if, bs_if);
                u64 ago = fma2(xs, wx_go, bs_go);
                const u64* hv = reinterpret_cast<const u64*>(h0ring[e][(n + 1) & 1]); // = (n-1)&1
#pragma unroll
                for (int k = 0; k < 32; k++) {
                    u64 h2 = hv[k];
                    aif = fma2(h2, w_if[k], aif);
                    ago = fma2(h2, w_go[k], ago);
                }
                float gi, gf, gg, go;
                unpack2(aif, gi, gf); unpack2(ago, gg, go);
                gi = sigm(gi); gf = sigm(gf); gg = tanhf_(gg); go = sigm(go);
                c = gf * c + gi * gg;
                float h = go * tanhf_(c);
                reinterpret_cast<u64*>(h0ring[e][n & 1])[j] = pack2(h, h);
                xt = xn;
            }
        } else if (role == 1) {
            if (n >= 1 && n <= T_SEQ) {
                const u64* hv = reinterpret_cast<const u64*>(h0ring[e][(n - 1) & 1]);
                u64 aif = bs_if, ago = bs_go;
#pragma unroll
                for (int k = 0; k < 32; k++) {
                    u64 h2 = hv[k];
                    aif = fma2(h2, w_if[k], aif);
                    ago = fma2(h2, w_go[k], ago);
                }
                pring[e][(n - 1) & 1][j]      = aif;
                pring[e][(n - 1) & 1][32 + j] = ago;
            }
        } else {
            if (n >= 2) {
                const int t = n - 2;
                const u64* pv = pring[e][n & 1];      // slot (n-2)&1 == n&1
                u64 aif = pv[j];
                u64 ago = pv[32 + j];
                const u64* hv = reinterpret_cast<const u64*>(h1buf[e]);
#pragma unroll
                for (int k = 0; k < 32; k++) {
                    u64 h2 = hv[k];
                    aif = fma2(h2, w_if[k], aif);
                    ago = fma2(h2, w_go[k], ago);
                }
                __syncwarp();   // all lanes done reading h1buf before overwrite
                float gi, gf, gg, go;
                unpack2(aif, gi, gf); unpack2(ago, gg, go);
                gi = sigm(gi); gf = sigm(gf); gg = tanhf_(gg); go = sigm(go);
                c = gf * c + gi * gg;
                float h = go * tanhf_(c);
                reinterpret_cast<u64*>(h1buf[e])[j] = pack2(h, h);
                g_h1[(size_t)t * (B_SZ * 32) + b * 32 + j] = h;   // coalesced 128B/warp
            }
        }
        __syncthreads();
    }
}

// =====================================================================
// Dense head: out[t,b] = sum_j h1[t,b,j]*Wd[j] + bd. Memory-bound.
// Warp covers 4 rows; lane j: row j>>3, float4 segment j&7. 3-shfl reduce.
// =====================================================================
__global__ void __launch_bounds__(256)
k_head(const float* __restrict__ Wd, const float* __restrict__ bd,
       float* __restrict__ out)
{
    const int gw = blockIdx.x * 8 + (threadIdx.x >> 5);
    const int j  = threadIdx.x & 31;
    const size_t r = (size_t)gw * 4 + (j >> 3);
    const int q  = j & 7;

    float4 h = reinterpret_cast<const float4*>(g_h1)[r * 8 + q];
    float4 w = reinterpret_cast<const float4*>(Wd)[q];
    float s = h.x * w.x + h.y * w.y + h.z * w.z + h.w * w.w;
    s += __shfl_xor_sync(0xffffffffu, s, 1);
    s += __shfl_xor_sync(0xffffffffu, s, 2);
    s += __shfl_xor_sync(0xffffffffu, s, 4);
    if (q == 0) out[r] = s + bd[0];
}

// =====================================================================
extern "C" void kernel_launch(void* const* d_in, const int* in_sizes, int n_in,
                              void* d_out, int out_size)
{
    const float* x    = (const float*)d_in[0];
    const float* Wih0 = (const float*)d_in[1];
    const float* Whh0 = (const float*)d_in[2];
    const float* bih0 = (const float*)d_in[3];
    const float* bhh0 = (const float*)d_in[4];
    const float* Wih1 = (const float*)d_in[5];
    const float* Whh1 = (const float*)d_in[6];
    const float* bih1 = (const float*)d_in[7];
    const float* bhh1 = (const float*)d_in[8];
    const float* Wd   = (const float*)d_in[9];
    const float* bd   = (const float*)d_in[10];

    k_fused<<<128, 384>>>(x, Wih0, Whh0, bih0, bhh0, Wih1, Whh1, bih1, bhh1);
    // rows = T*B = 1,048,576; 4 rows/warp, 8 warps/block -> 32768 blocks
    k_head<<<32768, 256>>>(Wd, bd, (float*)d_out);
}